// round 4
// baseline (speedup 1.0000x reference)
#include <cuda_runtime.h>
#include <math.h>

#define B_ROWS 16384
#define D_DIM  4096
#define H_DIM  128
#define E_DIM  64
#define NS     5

static constexpr float P_DROP = 0.3f;
static constexpr float SCALE  = (float)(1.0 / 0.7);
static constexpr float UNC_T  = 0.3f;

#define NT 512
#define BM 128
#define BK 64

// ---- shared memory layout (float offsets) ----
#define PITCH    132
#define OFF_SH   0
#define SH_SIZE  (128 * PITCH)             // 16896
#define OFF_HM   SH_SIZE                   // masked-h transposed [k][r]
#define HM_SIZE  (128 * PITCH)
#define OFF_AS   OFF_HM                    // phase-1 A tile aliases hM (64*132=8448)
#define OFF_BS   (OFF_AS + BK * PITCH)     // phase-1 B tile (64*128=8192) -> 16640 <= 16896
#define OFF_W2   (OFF_HM + HM_SIZE)        // 33792
#define OFF_B2   (OFF_W2 + H_DIM * E_DIM)  // 41984
#define SMEM_FLOATS (OFF_B2 + 64)
#define SMEM_BYTES  (SMEM_FLOATS * 4)      // 168192 B

typedef unsigned long long u64;

__device__ __forceinline__ u64 pack2(float a) {
    u64 r;
    asm("mov.b64 %0, {%1, %1};" : "=l"(r) : "r"(__float_as_uint(a)));
    return r;
}
__device__ __forceinline__ u64 pack2f(float a, float b) {
    u64 r;
    asm("mov.b64 %0, {%1, %2};" : "=l"(r) : "r"(__float_as_uint(a)), "r"(__float_as_uint(b)));
    return r;
}
__device__ __forceinline__ void unpack2(u64 v, float& a, float& b) {
    unsigned lo, hi;
    asm("mov.b64 {%0, %1}, %2;" : "=r"(lo), "=r"(hi) : "l"(v));
    a = __uint_as_float(lo);
    b = __uint_as_float(hi);
}
__device__ __forceinline__ void fma2(u64& d, u64 a, u64 b) {
    asm("fma.rn.f32x2 %0, %1, %2, %0;" : "+l"(d) : "l"(a), "l"(b));
}

__global__ __launch_bounds__(NT, 1)
void bayes_route_kernel(const float* __restrict__ x,
                        const float* __restrict__ W1,
                        const float* __restrict__ b1,
                        const float* __restrict__ W2,
                        const float* __restrict__ b2,
                        const float* __restrict__ m1u,
                        const float* __restrict__ m2u,
                        float* __restrict__ out)
{
    extern __shared__ __align__(16) float smem[];
    float* sH  = smem + OFF_SH;
    float* hM  = smem + OFF_HM;
    float* As  = smem + OFF_AS;
    float* Bs  = smem + OFF_BS;
    float* sW2 = smem + OFF_W2;
    float* sB2 = smem + OFF_B2;

    const int tid = threadIdx.x;
    const int tx  = tid & 15;          // 0..15 : 8-col group (phase1) / 4-expert group (phase2)
    const int ty2 = tid >> 4;          // 0..31 : 4-row group
    const int ro  = ty2 * 4;
    const int e8  = tx * 8;
    const int rowBase = blockIdx.x * BM;

    // ---- preload W2, b2 ----
    {
        const float4* w2v = (const float4*)W2;
        float4* sv = (float4*)sW2;
        #pragma unroll
        for (int i = tid; i < (H_DIM * E_DIM) / 4; i += NT) sv[i] = w2v[i];
        if (tid < E_DIM) sB2[tid] = b2[tid];
    }

    // =========================== Phase 1: h = relu(x@W1 + b1) ===========================
    // 128x128 tile, BK=64, 4 rows x 8 cols per thread, f32x2 accumulators.
    u64 acc[4][4];
    #pragma unroll
    for (int i = 0; i < 4; i++)
        #pragma unroll
        for (int j = 0; j < 4; j++) acc[i][j] = 0ull;

    const float* xp = x + (size_t)rowBase * D_DIM;

    // x-loader mapping: f = [k_hi:2][m:7][k_lo:2]  (4 float4 per thread)
    int xm[4], xk4[4], wk[4], wn4[4];
    #pragma unroll
    for (int i = 0; i < 4; i++) {
        int f = tid + (i << 9);
        int k_lo = f & 3;
        xm[i]  = (f >> 2) & 127;
        int k_hi = f >> 9;
        xk4[i] = (k_hi * 4 + k_lo) * 4;     // 0..60
        wk[i]  = f >> 5;                    // wait: recomputed below
        wn4[i] = 0;
    }
    // W1-loader mapping: f = tid + i*512 ; k = f>>5 (0..63), n4 = (f&31)*4
    #pragma unroll
    for (int i = 0; i < 4; i++) {
        int f = tid + (i << 9);
        wk[i]  = f >> 5;
        wn4[i] = (f & 31) * 4;
    }

    float4 px[4], pw[4];
    #pragma unroll
    for (int i = 0; i < 4; i++) {
        px[i] = *(const float4*)(xp + (size_t)xm[i] * D_DIM + xk4[i]);
        pw[i] = *(const float4*)(W1 + (size_t)wk[i] * H_DIM + wn4[i]);
    }

    const int nIter = D_DIM / BK;    // 64
    for (int kt = 0; kt < nIter; kt++) {
        __syncthreads();             // previous compute done reading As/Bs
        #pragma unroll
        for (int i = 0; i < 4; i++) {
            const float* pf = (const float*)&px[i];
            int m = xm[i], k4 = xk4[i];
            As[(k4 + 0) * PITCH + m] = pf[0];
            As[(k4 + 1) * PITCH + m] = pf[1];
            As[(k4 + 2) * PITCH + m] = pf[2];
            As[(k4 + 3) * PITCH + m] = pf[3];
            *(float4*)(Bs + wk[i] * H_DIM + wn4[i]) = pw[i];
        }
        __syncthreads();
        if (kt + 1 < nIter) {
            int kb = (kt + 1) * BK;
            #pragma unroll
            for (int i = 0; i < 4; i++) {
                px[i] = *(const float4*)(xp + (size_t)xm[i] * D_DIM + kb + xk4[i]);
                pw[i] = *(const float4*)(W1 + (size_t)(kb + wk[i]) * H_DIM + wn4[i]);
            }
        }
        #pragma unroll 8
        for (int k = 0; k < BK; k++) {
            float4 a0 = *(const float4*)(As + k * PITCH + ro);
            ulonglong2 bq0 = *(const ulonglong2*)(Bs + k * H_DIM + e8);
            ulonglong2 bq1 = *(const ulonglong2*)(Bs + k * H_DIM + e8 + 4);
            float av[4] = {a0.x, a0.y, a0.z, a0.w};
            #pragma unroll
            for (int i = 0; i < 4; i++) {
                u64 aa = pack2(av[i]);
                fma2(acc[i][0], aa, bq0.x);
                fma2(acc[i][1], aa, bq0.y);
                fma2(acc[i][2], aa, bq1.x);
                fma2(acc[i][3], aa, bq1.y);
            }
        }
    }
    __syncthreads();   // done with As/Bs

    // epilogue: bias + relu -> sH row-major
    {
        float4 b1a = *(const float4*)(b1 + e8);
        float4 b1b = *(const float4*)(b1 + e8 + 4);
        float bf[8] = {b1a.x, b1a.y, b1a.z, b1a.w, b1b.x, b1b.y, b1b.z, b1b.w};
        #pragma unroll
        for (int i = 0; i < 4; i++) {
            int rr = ro + i;
            float h[8];
            unpack2(acc[i][0], h[0], h[1]);
            unpack2(acc[i][1], h[2], h[3]);
            unpack2(acc[i][2], h[4], h[5]);
            unpack2(acc[i][3], h[6], h[7]);
            #pragma unroll
            for (int j = 0; j < 8; j++) h[j] = fmaxf(h[j] + bf[j], 0.f);
            *(float4*)(sH + rr * PITCH + e8)     = make_float4(h[0], h[1], h[2], h[3]);
            *(float4*)(sH + rr * PITCH + e8 + 4) = make_float4(h[4], h[5], h[6], h[7]);
        }
    }
    __syncthreads();

    // =========================== Phase 2: 5 samples ===========================
    const int e0 = tx * 4;     // 4 experts per thread

    float sumL[4][4], sumP[4][4], sumP2[4][4];
    #pragma unroll
    for (int i = 0; i < 4; i++)
        #pragma unroll
        for (int j = 0; j < 4; j++) { sumL[i][j] = 0.f; sumP[i][j] = 0.f; sumP2[i][j] = 0.f; }

    const u64 ib0 = pack2f(sB2[e0], sB2[e0 + 1]);
    const u64 ib1 = pack2f(sB2[e0 + 2], sB2[e0 + 3]);

    for (int s = 0; s < NS; s++) {
        // ---- build masked transposed tile hM[k][r] (linear coalesced mapping) ----
        __syncthreads();  // previous GEMM done reading hM
        {
            const float4* m1base = (const float4*)(m1u + ((size_t)s * B_ROWS + rowBase) * H_DIM);
            #pragma unroll
            for (int it = 0; it < 8; it++) {
                int idx = tid + it * NT;        // 0..4095 over tile float4s
                int row = idx >> 5;             // 0..127
                int kq  = idx & 31;             // float4 within row
                float4 mu = m1base[idx];
                float4 hv = *(const float4*)(sH + row * PITCH + kq * 4);
                int kb = kq * 4;
                hM[(kb + 0) * PITCH + row] = (mu.x >= P_DROP) ? hv.x * SCALE : 0.f;
                hM[(kb + 1) * PITCH + row] = (mu.y >= P_DROP) ? hv.y * SCALE : 0.f;
                hM[(kb + 2) * PITCH + row] = (mu.z >= P_DROP) ? hv.z * SCALE : 0.f;
                hM[(kb + 3) * PITCH + row] = (mu.w >= P_DROP) ? hv.w * SCALE : 0.f;
            }
        }
        __syncthreads();

        // ---- logits[128x64] = hM^T @ W2 : 4 rows x 4 experts per thread ----
        u64 lacc[4][2];
        #pragma unroll
        for (int i = 0; i < 4; i++) { lacc[i][0] = ib0; lacc[i][1] = ib1; }

        #pragma unroll 8
        for (int k = 0; k < H_DIM; k++) {
            float4 a0 = *(const float4*)(hM + k * PITCH + ro);
            ulonglong2 bb = *(const ulonglong2*)(sW2 + k * E_DIM + e0);
            float av[4] = {a0.x, a0.y, a0.z, a0.w};
            #pragma unroll
            for (int i = 0; i < 4; i++) {
                u64 aa = pack2(av[i]);
                fma2(lacc[i][0], aa, bb.x);
                fma2(lacc[i][1], aa, bb.y);
            }
        }

        // ---- mask2, per-row softmax (reduce over 16 tx lanes), stats ----
        #pragma unroll
        for (int i = 0; i < 4; i++) {
            size_t row = (size_t)rowBase + ro + i;
            float4 mu = *(const float4*)(m2u + ((size_t)s * B_ROWS + row) * E_DIM + e0);
            float l[4];
            unpack2(lacc[i][0], l[0], l[1]);
            unpack2(lacc[i][1], l[2], l[3]);
            l[0] *= (mu.x >= P_DROP) ? SCALE : 0.f;
            l[1] *= (mu.y >= P_DROP) ? SCALE : 0.f;
            l[2] *= (mu.z >= P_DROP) ? SCALE : 0.f;
            l[3] *= (mu.w >= P_DROP) ? SCALE : 0.f;
            float mx = fmaxf(fmaxf(l[0], l[1]), fmaxf(l[2], l[3]));
            #pragma unroll
            for (int j = 0; j < 4; j++) sumL[i][j] += l[j];
            #pragma unroll
            for (int off = 1; off < 16; off <<= 1)
                mx = fmaxf(mx, __shfl_xor_sync(0xFFFFFFFFu, mx, off));
            float ex[4];
            float ss = 0.f;
            #pragma unroll
            for (int j = 0; j < 4; j++) { ex[j] = __expf(l[j] - mx); ss += ex[j]; }
            #pragma unroll
            for (int off = 1; off < 16; off <<= 1)
                ss += __shfl_xor_sync(0xFFFFFFFFu, ss, off);
            float inv = 1.f / ss;
            #pragma unroll
            for (int j = 0; j < 4; j++) {
                float pe = ex[j] * inv;
                sumP[i][j] += pe;
                sumP2[i][j] = fmaf(pe, pe, sumP2[i][j]);
            }
        }
    }

    // =========================== Final: mean softmax, uncertainty, top-4 ===========================
    #pragma unroll
    for (int i = 0; i < 4; i++) {
        float p[4];
        float mx = -1e30f;
        #pragma unroll
        for (int j = 0; j < 4; j++) { p[j] = sumL[i][j] * 0.2f; mx = fmaxf(mx, p[j]); }
        #pragma unroll
        for (int off = 1; off < 16; off <<= 1)
            mx = fmaxf(mx, __shfl_xor_sync(0xFFFFFFFFu, mx, off));
        float ss = 0.f;
        #pragma unroll
        for (int j = 0; j < 4; j++) { p[j] = __expf(p[j] - mx); ss += p[j]; }
        #pragma unroll
        for (int off = 1; off < 16; off <<= 1)
            ss += __shfl_xor_sync(0xFFFFFFFFu, ss, off);
        float inv = 1.f / ss;
        #pragma unroll
        for (int j = 0; j < 4; j++) p[j] *= inv;

        float us = 0.f;
        #pragma unroll
        for (int j = 0; j < 4; j++) {
            float mean = sumP[i][j] * 0.2f;
            float var  = (sumP2[i][j] - 5.f * mean * mean) * 0.25f;
            us += sqrtf(fmaxf(var, 0.f));
        }
        #pragma unroll
        for (int off = 1; off < 16; off <<= 1)
            us += __shfl_xor_sync(0xFFFFFFFFu, us, off);
        float unc = us * (1.f / 64.f);

        // top-4 over 64 experts; ties -> lower index
        float fv[4];
        int   fi[4];
        #pragma unroll
        for (int t = 0; t < 4; t++) {
            float bv = p[0]; int bi = e0;
            #pragma unroll
            for (int j = 1; j < 4; j++)
                if (p[j] > bv) { bv = p[j]; bi = e0 + j; }
            #pragma unroll
            for (int off = 1; off < 16; off <<= 1) {
                float ov = __shfl_xor_sync(0xFFFFFFFFu, bv, off);
                int   oi = __shfl_xor_sync(0xFFFFFFFFu, bi, off);
                if (ov > bv || (ov == bv && oi < bi)) { bv = ov; bi = oi; }
            }
            fv[t] = bv; fi[t] = bi;
            #pragma unroll
            for (int j = 0; j < 4; j++)
                if (e0 + j == bi) p[j] = -2.f;
        }

        if (tx == 0) {
            size_t grow = (size_t)rowBase + ro + i;
            bool uncertain = unc > UNC_T;
            float* oIdx = out;
            float* oP   = out + (size_t)B_ROWS * 4;
            float* oU   = out + (size_t)B_ROWS * 8;
            oIdx[grow * 4 + 0] = (float)fi[0];
            oIdx[grow * 4 + 1] = (float)fi[1];
            oIdx[grow * 4 + 2] = uncertain ? (float)fi[2] : -1.f;
            oIdx[grow * 4 + 3] = uncertain ? (float)fi[3] : -1.f;
            oP[grow * 4 + 0] = fv[0];
            oP[grow * 4 + 1] = fv[1];
            oP[grow * 4 + 2] = uncertain ? fv[2] : 0.f;
            oP[grow * 4 + 3] = uncertain ? fv[3] : 0.f;
            oU[grow] = unc;
        }
    }
}

extern "C" void kernel_launch(void* const* d_in, const int* in_sizes, int n_in,
                              void* d_out, int out_size)
{
    (void)in_sizes; (void)n_in; (void)out_size;
    const float* x   = (const float*)d_in[0];
    const float* W1  = (const float*)d_in[1];
    const float* b1  = (const float*)d_in[2];
    const float* W2  = (const float*)d_in[3];
    const float* b2  = (const float*)d_in[4];
    const float* m1u = (const float*)d_in[5];
    const float* m2u = (const float*)d_in[6];
    float* out = (float*)d_out;

    cudaFuncSetAttribute(bayes_route_kernel,
                         cudaFuncAttributeMaxDynamicSharedMemorySize, SMEM_BYTES);
    bayes_route_kernel<<<B_ROWS / BM, NT, SMEM_BYTES>>>(
        x, W1, b1, W2, b2, m1u, m2u, out);
}

// round 5
// speedup vs baseline: 2.5961x; 2.5961x over previous
#include <cuda_runtime.h>
#include <math.h>

#define B_ROWS 16384
#define D_DIM  4096
#define H_DIM  128
#define E_DIM  64
#define NS     5

static constexpr float P_DROP = 0.3f;
static constexpr float SCALE  = (float)(1.0 / 0.7);
static constexpr float UNC_T  = 0.3f;

#define NT 256
#define BM 128
#define BK 32

// ---- shared memory layout (float offsets) ----
#define PITCH    132
#define OFF_SH   0
#define SH_SIZE  (128 * PITCH)             // 16896
#define OFF_HM   SH_SIZE                   // masked-h transposed [k][r]
#define HM_SIZE  (128 * PITCH)
// phase-1 double-buffered tiles alias the hM region:
#define ABUF     (BK * PITCH)              // 4224
#define BBUF     (BK * H_DIM)              // 4096
#define OFF_AS   OFF_HM
#define OFF_BS   (OFF_HM + 2 * ABUF)       // + 8448 ; total 16640 <= 16896
#define OFF_W2   (OFF_HM + HM_SIZE)        // 33792
#define OFF_B2   (OFF_W2 + H_DIM * E_DIM)  // 41984
#define SMEM_FLOATS (OFF_B2 + 64)
#define SMEM_BYTES  (SMEM_FLOATS * 4)      // 168192 B

typedef unsigned long long u64;

__device__ __forceinline__ u64 pack2(float a) {
    u64 r;
    asm("mov.b64 %0, {%1, %1};" : "=l"(r) : "r"(__float_as_uint(a)));
    return r;
}
__device__ __forceinline__ u64 pack2f(float a, float b) {
    u64 r;
    asm("mov.b64 %0, {%1, %2};" : "=l"(r) : "r"(__float_as_uint(a)), "r"(__float_as_uint(b)));
    return r;
}
__device__ __forceinline__ void unpack2(u64 v, float& a, float& b) {
    unsigned lo, hi;
    asm("mov.b64 {%0, %1}, %2;" : "=r"(lo), "=r"(hi) : "l"(v));
    a = __uint_as_float(lo);
    b = __uint_as_float(hi);
}
__device__ __forceinline__ void fma2(u64& d, u64 a, u64 b) {
    asm("fma.rn.f32x2 %0, %1, %2, %0;" : "+l"(d) : "l"(a), "l"(b));
}

__global__ __launch_bounds__(NT, 1)
void bayes_route_kernel(const float* __restrict__ x,
                        const float* __restrict__ W1,
                        const float* __restrict__ b1,
                        const float* __restrict__ W2,
                        const float* __restrict__ b2,
                        const float* __restrict__ m1u,
                        const float* __restrict__ m2u,
                        float* __restrict__ out)
{
    extern __shared__ __align__(16) float smem[];
    float* sH  = smem + OFF_SH;
    float* hM  = smem + OFF_HM;
    float* sW2 = smem + OFF_W2;
    float* sB2 = smem + OFF_B2;

    const int tid = threadIdx.x;
    const int tx  = tid & 15;          // 0..15
    const int ty  = tid >> 4;          // 0..15
    const int rowBase = blockIdx.x * BM;

    // split-fragment coordinates (conflict-free B loads)
    const int r0 = ty * 4;             // rows r0..r0+3 and 64+r0..64+r0+3
    const int c0 = tx * 4;             // cols c0..c0+3 and 64+c0..64+c0+3

    // ---- preload W2, b2 ----
    {
        const float4* w2v = (const float4*)W2;
        float4* sv = (float4*)sW2;
        #pragma unroll
        for (int i = tid; i < (H_DIM * E_DIM) / 4; i += NT) sv[i] = w2v[i];
        if (tid < E_DIM) sB2[tid] = b2[tid];
    }

    // =========================== Phase 1: h = relu(x@W1 + b1) ===========================
    u64 acc[8][4];
    #pragma unroll
    for (int i = 0; i < 8; i++)
        #pragma unroll
        for (int j = 0; j < 4; j++) acc[i][j] = 0ull;

    const float* xp = x + (size_t)rowBase * D_DIM;

    // loader mappings: 1024 float4 per tile, 4 per thread
    int xm[4], xk4[4], wk[4], wn4[4];
    #pragma unroll
    for (int i = 0; i < 4; i++) {
        int f = tid + (i << 8);
        xm[i]  = f >> 3;              // 0..127
        xk4[i] = (f & 7) * 4;         // 0..28
        wk[i]  = f >> 5;              // 0..31
        wn4[i] = (f & 31) * 4;        // 0..124
    }

    float4 px[4], pw[4];
    #pragma unroll
    for (int i = 0; i < 4; i++) {
        px[i] = *(const float4*)(xp + (size_t)xm[i] * D_DIM + xk4[i]);
        pw[i] = *(const float4*)(W1 + (size_t)wk[i] * H_DIM + wn4[i]);
    }
    // prologue store into buffer 0
    #pragma unroll
    for (int i = 0; i < 4; i++) {
        const float* pf = (const float*)&px[i];
        int m = xm[i], k4 = xk4[i];
        float* As0 = smem + OFF_AS;
        As0[(k4 + 0) * PITCH + m] = pf[0];
        As0[(k4 + 1) * PITCH + m] = pf[1];
        As0[(k4 + 2) * PITCH + m] = pf[2];
        As0[(k4 + 3) * PITCH + m] = pf[3];
        *(float4*)(smem + OFF_BS + wk[i] * H_DIM + wn4[i]) = pw[i];
    }
    __syncthreads();

    const int nIter = D_DIM / BK;      // 128
    #pragma unroll 1
    for (int kt = 0; kt < nIter; kt++) {
        const int cur = kt & 1;
        const float* Asc = smem + OFF_AS + cur * ABUF;
        const float* Bsc = smem + OFF_BS + cur * BBUF;

        if (kt + 1 < nIter) {
            int kb = (kt + 1) * BK;
            #pragma unroll
            for (int i = 0; i < 4; i++) {
                px[i] = *(const float4*)(xp + (size_t)xm[i] * D_DIM + kb + xk4[i]);
                pw[i] = *(const float4*)(W1 + (size_t)(kb + wk[i]) * H_DIM + wn4[i]);
            }
        }

        #pragma unroll 8
        for (int k = 0; k < BK; k++) {
            float4 a0 = *(const float4*)(Asc + k * PITCH + r0);
            float4 a1 = *(const float4*)(Asc + k * PITCH + 64 + r0);
            ulonglong2 b0 = *(const ulonglong2*)(Bsc + k * H_DIM + c0);
            ulonglong2 b1v = *(const ulonglong2*)(Bsc + k * H_DIM + 64 + c0);
            float av[8] = {a0.x, a0.y, a0.z, a0.w, a1.x, a1.y, a1.z, a1.w};
            #pragma unroll
            for (int i = 0; i < 8; i++) {
                u64 aa = pack2(av[i]);
                fma2(acc[i][0], aa, b0.x);
                fma2(acc[i][1], aa, b0.y);
                fma2(acc[i][2], aa, b1v.x);
                fma2(acc[i][3], aa, b1v.y);
            }
        }

        if (kt + 1 < nIter) {
            float* Asn = smem + OFF_AS + (cur ^ 1) * ABUF;
            float* Bsn = smem + OFF_BS + (cur ^ 1) * BBUF;
            #pragma unroll
            for (int i = 0; i < 4; i++) {
                const float* pf = (const float*)&px[i];
                int m = xm[i], k4 = xk4[i];
                Asn[(k4 + 0) * PITCH + m] = pf[0];
                Asn[(k4 + 1) * PITCH + m] = pf[1];
                Asn[(k4 + 2) * PITCH + m] = pf[2];
                Asn[(k4 + 3) * PITCH + m] = pf[3];
                *(float4*)(Bsn + wk[i] * H_DIM + wn4[i]) = pw[i];
            }
        }
        __syncthreads();
    }

    // epilogue: bias + relu -> sH row-major (rows r0..+3 / 64+r0..+3, cols c0..+3 / 64+c0..+3)
    {
        float4 bca = *(const float4*)(b1 + c0);
        float4 bcb = *(const float4*)(b1 + 64 + c0);
        float bf[8] = {bca.x, bca.y, bca.z, bca.w, bcb.x, bcb.y, bcb.z, bcb.w};
        #pragma unroll
        for (int i = 0; i < 8; i++) {
            int rr = (i < 4) ? (r0 + i) : (64 + r0 + i - 4);
            float h[8];
            unpack2(acc[i][0], h[0], h[1]);
            unpack2(acc[i][1], h[2], h[3]);
            unpack2(acc[i][2], h[4], h[5]);
            unpack2(acc[i][3], h[6], h[7]);
            #pragma unroll
            for (int j = 0; j < 4; j++) h[j]     = fmaxf(h[j]     + bf[j],     0.f);
            #pragma unroll
            for (int j = 0; j < 4; j++) h[4 + j] = fmaxf(h[4 + j] + bf[4 + j], 0.f);
            *(float4*)(sH + rr * PITCH + c0)      = make_float4(h[0], h[1], h[2], h[3]);
            *(float4*)(sH + rr * PITCH + 64 + c0) = make_float4(h[4], h[5], h[6], h[7]);
        }
    }
    __syncthreads();

    // =========================== Phase 2: 5 samples ===========================
    const int e0 = tx * 4;     // 4 experts per thread
    const int ro = ty * 8;     // 8 rows per thread

    float sumL[8][4], sumP[8][4], sumP2[8][4];
    #pragma unroll
    for (int i = 0; i < 8; i++)
        #pragma unroll
        for (int j = 0; j < 4; j++) { sumL[i][j] = 0.f; sumP[i][j] = 0.f; sumP2[i][j] = 0.f; }

    const u64 ib0 = pack2f(sB2[e0], sB2[e0 + 1]);
    const u64 ib1 = pack2f(sB2[e0 + 2], sB2[e0 + 3]);

    const int mr  = tid & 127;      // masking: row
    const int mkh = tid >> 7;       // masking: k half (0/1)

    for (int s = 0; s < NS; s++) {
        // ---- build masked transposed tile hM[k][r] ----
        __syncthreads();  // previous GEMM done reading hM
        {
            const float4* mrow = (const float4*)(m1u +
                ((size_t)s * B_ROWS + rowBase + mr) * H_DIM + mkh * 64);
            const float4* hrow = (const float4*)(sH + mr * PITCH + mkh * 64);
            #pragma unroll
            for (int q = 0; q < 16; q++) {
                float4 mu = mrow[q];
                float4 hv = hrow[q];
                int kb = mkh * 64 + q * 4;
                hM[(kb + 0) * PITCH + mr] = (mu.x >= P_DROP) ? hv.x * SCALE : 0.f;
                hM[(kb + 1) * PITCH + mr] = (mu.y >= P_DROP) ? hv.y * SCALE : 0.f;
                hM[(kb + 2) * PITCH + mr] = (mu.z >= P_DROP) ? hv.z * SCALE : 0.f;
                hM[(kb + 3) * PITCH + mr] = (mu.w >= P_DROP) ? hv.w * SCALE : 0.f;
            }
        }
        __syncthreads();

        // ---- logits[128x64] = hM^T @ W2 : 8 rows x 4 experts per thread ----
        u64 lacc[8][2];
        #pragma unroll
        for (int i = 0; i < 8; i++) { lacc[i][0] = ib0; lacc[i][1] = ib1; }

        #pragma unroll 4
        for (int k = 0; k < H_DIM; k++) {
            float4 a0 = *(const float4*)(hM + k * PITCH + ro);
            float4 a1 = *(const float4*)(hM + k * PITCH + ro + 4);
            ulonglong2 bb = *(const ulonglong2*)(sW2 + k * E_DIM + e0);
            float av[8] = {a0.x, a0.y, a0.z, a0.w, a1.x, a1.y, a1.z, a1.w};
            #pragma unroll
            for (int i = 0; i < 8; i++) {
                u64 aa = pack2(av[i]);
                fma2(lacc[i][0], aa, bb.x);
                fma2(lacc[i][1], aa, bb.y);
            }
        }

        // ---- mask2, per-row softmax (reduce over 16 tx lanes), stats ----
        #pragma unroll
        for (int i = 0; i < 8; i++) {
            size_t row = (size_t)rowBase + ro + i;
            float4 mu = *(const float4*)(m2u + ((size_t)s * B_ROWS + row) * E_DIM + e0);
            float l[4];
            unpack2(lacc[i][0], l[0], l[1]);
            unpack2(lacc[i][1], l[2], l[3]);
            l[0] *= (mu.x >= P_DROP) ? SCALE : 0.f;
            l[1] *= (mu.y >= P_DROP) ? SCALE : 0.f;
            l[2] *= (mu.z >= P_DROP) ? SCALE : 0.f;
            l[3] *= (mu.w >= P_DROP) ? SCALE : 0.f;
            float mx = fmaxf(fmaxf(l[0], l[1]), fmaxf(l[2], l[3]));
            #pragma unroll
            for (int j = 0; j < 4; j++) sumL[i][j] += l[j];
            #pragma unroll
            for (int off = 1; off < 16; off <<= 1)
                mx = fmaxf(mx, __shfl_xor_sync(0xFFFFFFFFu, mx, off));
            float ex[4];
            float ss = 0.f;
            #pragma unroll
            for (int j = 0; j < 4; j++) { ex[j] = __expf(l[j] - mx); ss += ex[j]; }
            #pragma unroll
            for (int off = 1; off < 16; off <<= 1)
                ss += __shfl_xor_sync(0xFFFFFFFFu, ss, off);
            float inv = 1.f / ss;
            #pragma unroll
            for (int j = 0; j < 4; j++) {
                float pe = ex[j] * inv;
                sumP[i][j] += pe;
                sumP2[i][j] = fmaf(pe, pe, sumP2[i][j]);
            }
        }
    }

    // =========================== Final: mean softmax, uncertainty, top-4 ===========================
    #pragma unroll
    for (int i = 0; i < 8; i++) {
        float p[4];
        float mx = -1e30f;
        #pragma unroll
        for (int j = 0; j < 4; j++) { p[j] = sumL[i][j] * 0.2f; mx = fmaxf(mx, p[j]); }
        #pragma unroll
        for (int off = 1; off < 16; off <<= 1)
            mx = fmaxf(mx, __shfl_xor_sync(0xFFFFFFFFu, mx, off));
        float ss = 0.f;
        #pragma unroll
        for (int j = 0; j < 4; j++) { p[j] = __expf(p[j] - mx); ss += p[j]; }
        #pragma unroll
        for (int off = 1; off < 16; off <<= 1)
            ss += __shfl_xor_sync(0xFFFFFFFFu, ss, off);
        float inv = 1.f / ss;
        #pragma unroll
        for (int j = 0; j < 4; j++) p[j] *= inv;

        float us = 0.f;
        #pragma unroll
        for (int j = 0; j < 4; j++) {
            float mean = sumP[i][j] * 0.2f;
            float var  = (sumP2[i][j] - 5.f * mean * mean) * 0.25f;
            us += sqrtf(fmaxf(var, 0.f));
        }
        #pragma unroll
        for (int off = 1; off < 16; off <<= 1)
            us += __shfl_xor_sync(0xFFFFFFFFu, us, off);
        float unc = us * (1.f / 64.f);

        // top-4 over 64 experts; ties -> lower index
        float fv[4];
        int   fi[4];
        #pragma unroll
        for (int t = 0; t < 4; t++) {
            float bv = p[0]; int bi = e0;
            #pragma unroll
            for (int j = 1; j < 4; j++)
                if (p[j] > bv) { bv = p[j]; bi = e0 + j; }
            #pragma unroll
            for (int off = 1; off < 16; off <<= 1) {
                float ov = __shfl_xor_sync(0xFFFFFFFFu, bv, off);
                int   oi = __shfl_xor_sync(0xFFFFFFFFu, bi, off);
                if (ov > bv || (ov == bv && oi < bi)) { bv = ov; bi = oi; }
            }
            fv[t] = bv; fi[t] = bi;
            #pragma unroll
            for (int j = 0; j < 4; j++)
                if (e0 + j == bi) p[j] = -2.f;
        }

        if (tx == 0) {
            size_t grow = (size_t)rowBase + ro + i;
            bool uncertain = unc > UNC_T;
            float* oIdx = out;
            float* oP   = out + (size_t)B_ROWS * 4;
            float* oU   = out + (size_t)B_ROWS * 8;
            oIdx[grow * 4 + 0] = (float)fi[0];
            oIdx[grow * 4 + 1] = (float)fi[1];
            oIdx[grow * 4 + 2] = uncertain ? (float)fi[2] : -1.f;
            oIdx[grow * 4 + 3] = uncertain ? (float)fi[3] : -1.f;
            oP[grow * 4 + 0] = fv[0];
            oP[grow * 4 + 1] = fv[1];
            oP[grow * 4 + 2] = uncertain ? fv[2] : 0.f;
            oP[grow * 4 + 3] = uncertain ? fv[3] : 0.f;
            oU[grow] = unc;
        }
    }
}

extern "C" void kernel_launch(void* const* d_in, const int* in_sizes, int n_in,
                              void* d_out, int out_size)
{
    (void)in_sizes; (void)n_in; (void)out_size;
    const float* x   = (const float*)d_in[0];
    const float* W1  = (const float*)d_in[1];
    const float* b1  = (const float*)d_in[2];
    const float* W2  = (const float*)d_in[3];
    const float* b2  = (const float*)d_in[4];
    const float* m1u = (const float*)d_in[5];
    const float* m2u = (const float*)d_in[6];
    float* out = (float*)d_out;

    cudaFuncSetAttribute(bayes_route_kernel,
                         cudaFuncAttributeMaxDynamicSharedMemorySize, SMEM_BYTES);
    bayes_route_kernel<<<B_ROWS / BM, NT, SMEM_BYTES>>>(
        x, W1, b1, W2, b2, m1u, m2u, out);
}